// round 7
// baseline (speedup 1.0000x reference)
#include <cuda_runtime.h>
#include <cstdint>

// Problem constants (dataset-fixed): B=64, T=512, F=1024, H=31, G=4H=124
#define B_SZ 64
#define T_SZ 512
#define F_SZ 1024
#define H_SZ 31
#define G_SZ 124
#define ROWS (B_SZ * T_SZ)      // 32768
#define XG_STRIDE 128           // padded gate stride

// ---------------- scratch (no allocations allowed) ----------------
__device__ float g_xg[(size_t)ROWS * XG_STRIDE];      // gates1 x-part + bias
__device__ float g_h2hist[(size_t)ROWS * 32];         // h2 per step, [b*T+t][32]

// ---------------- accurate activations (fast-math-proof) ----------------
__device__ __forceinline__ float exp_acc(float x) {
    x = fminf(fmaxf(x, -87.0f), 87.0f);
    float t = fmaf(x, 1.4426950408889634f, 12582912.0f);
    float kf = t - 12582912.0f;
    int k = (int)kf;
    float r = fmaf(kf, -0.693145751953125f, x);
    r = fmaf(kf, -1.42860676533018681e-6f, r);
    float p = 1.9841269841e-4f;
    p = fmaf(p, r, 1.3888888889e-3f);
    p = fmaf(p, r, 8.3333333333e-3f);
    p = fmaf(p, r, 4.1666666667e-2f);
    p = fmaf(p, r, 1.6666666667e-1f);
    p = fmaf(p, r, 0.5f);
    p = fmaf(p, r, 1.0f);
    p = fmaf(p, r, 1.0f);
    return p * __int_as_float((k + 127) << 23);
}
__device__ __forceinline__ float sigf(float x) {
    return __fdiv_rn(1.0f, 1.0f + exp_acc(-x));
}
__device__ __forceinline__ float tanh_acc(float x) {
    float ax = fabsf(x);
    if (ax < 0.625f) {
        float z = x * x;
        float p = -5.70498872745e-3f;
        p = fmaf(p, z, 2.06390887954e-2f);
        p = fmaf(p, z, -5.37397155531e-2f);
        p = fmaf(p, z, 1.33314422036e-1f);
        p = fmaf(p, z, -3.33332819422e-1f);
        return fmaf(x * z, p, x);
    } else {
        float e = exp_acc(2.0f * ax);
        float r = 1.0f - __fdiv_rn(2.0f, e + 1.0f);
        return copysignf(r, x);
    }
}

// 32-wide dot (padded rows, operands 16B-aligned in smem)
__device__ __forceinline__ float dot32(const float* __restrict__ w,
                                       const float* __restrict__ h) {
    float a0 = 0.f, a1 = 0.f, a2 = 0.f, a3 = 0.f;
#pragma unroll
    for (int k = 0; k < 32; k += 4) {
        float4 wv = *(const float4*)(w + k);
        float4 hv = *(const float4*)(h + k);
        a0 = fmaf(wv.x, hv.x, a0);
        a1 = fmaf(wv.y, hv.y, a1);
        a2 = fmaf(wv.z, hv.z, a2);
        a3 = fmaf(wv.w, hv.w, a3);
    }
    return (a0 + a1) + (a2 + a3);
}

// LSTM pointwise via intra-quad shuffles; every lane of the quad keeps c.
__device__ __forceinline__ float lstm_unit(float myg, int lanebase, float& c) {
    float vi = __shfl_sync(0xffffffffu, myg, lanebase + 0);
    float vf = __shfl_sync(0xffffffffu, myg, lanebase + 1);
    float vg = __shfl_sync(0xffffffffu, myg, lanebase + 2);
    float vo = __shfl_sync(0xffffffffu, myg, lanebase + 3);
    c = vf * c + vi * vg;
    return vo * tanh_acc(c);
}

// =================================================================
// Kernel 1: xg[r][g] = x_r . W_ih1[g,:] + b_ih1[g] + b_hh1[g]
// M=32768, N=124(pad128), K=1024. BM=128,BN=128,BK=16, 256 thr, 8x8/thread.
// =================================================================
__global__ __launch_bounds__(256) void gemm_xg_kernel(
    const float* __restrict__ x, const float* __restrict__ W,
    const float* __restrict__ b_ih, const float* __restrict__ b_hh) {
    __shared__ float xs[16][128];   // [k][row]
    __shared__ float ws[16][128];   // [k][col]

    const int tid = threadIdx.x;
    const int row0 = blockIdx.x * 128;
    const int tx = tid & 15;        // col group
    const int ty = tid >> 4;        // row group
    const int c0 = tx * 8;
    const int r0 = ty * 8;

    float acc[8][8];
#pragma unroll
    for (int i = 0; i < 8; i++)
#pragma unroll
        for (int j = 0; j < 8; j++) acc[i][j] = 0.f;

    for (int k0 = 0; k0 < F_SZ; k0 += 16) {
        // x tile: 128 rows x 16 k = 512 float4 (2/thread)
#pragma unroll
        for (int l = tid; l < 512; l += 256) {
            int r = l >> 2;
            int kq = (l & 3) << 2;
            float4 v = *(const float4*)(x + (size_t)(row0 + r) * F_SZ + k0 + kq);
            xs[kq + 0][r] = v.x; xs[kq + 1][r] = v.y;
            xs[kq + 2][r] = v.z; xs[kq + 3][r] = v.w;
        }
        // W tile: 128 cols x 16 k = 512 float4 (2/thread), pad col>=124
#pragma unroll
        for (int l = tid; l < 512; l += 256) {
            int gc = l >> 2;
            int kq = (l & 3) << 2;
            float4 v = make_float4(0.f, 0.f, 0.f, 0.f);
            if (gc < G_SZ) v = *(const float4*)(W + (size_t)gc * F_SZ + k0 + kq);
            ws[kq + 0][gc] = v.x; ws[kq + 1][gc] = v.y;
            ws[kq + 2][gc] = v.z; ws[kq + 3][gc] = v.w;
        }
        __syncthreads();

#pragma unroll
        for (int kk = 0; kk < 16; kk++) {
            float4 xa = *(const float4*)&xs[kk][r0];
            float4 xb = *(const float4*)&xs[kk][r0 + 4];
            float4 wa = *(const float4*)&ws[kk][c0];
            float4 wb = *(const float4*)&ws[kk][c0 + 4];
            float xr[8] = {xa.x, xa.y, xa.z, xa.w, xb.x, xb.y, xb.z, xb.w};
            float wr[8] = {wa.x, wa.y, wa.z, wa.w, wb.x, wb.y, wb.z, wb.w};
#pragma unroll
            for (int i = 0; i < 8; i++)
#pragma unroll
                for (int j = 0; j < 8; j++)
                    acc[i][j] = fmaf(xr[i], wr[j], acc[i][j]);
        }
        __syncthreads();
    }

    float bs[8];
#pragma unroll
    for (int j = 0; j < 8; j++) {
        int cc = c0 + j;
        bs[j] = (cc < G_SZ) ? (b_ih[cc] + b_hh[cc]) : 0.f;
    }
#pragma unroll
    for (int i = 0; i < 8; i++) {
        int r = row0 + r0 + i;
        float4 lo = make_float4(acc[i][0] + bs[0], acc[i][1] + bs[1],
                                acc[i][2] + bs[2], acc[i][3] + bs[3]);
        float4 hi = make_float4(acc[i][4] + bs[4], acc[i][5] + bs[5],
                                acc[i][6] + bs[6], acc[i][7] + bs[7]);
        *(float4*)&g_xg[(size_t)r * XG_STRIDE + c0] = lo;
        *(float4*)&g_xg[(size_t)r * XG_STRIDE + c0 + 4] = hi;
    }
}

// =================================================================
// Kernel 2: recurrence, unit-major gates (thread g = 4u+q), shuffle
//           activations, 2 barriers/step, padded float4 dots.
// =================================================================
#define ROFF_WHH1 0                     // 128*32 = 4096 (rows >=124 zero)
#define ROFF_WIH2 4096
#define ROFF_WHH2 8192
#define ROFF_WLIN 12288                 // 1024*32 = 32768 (k=31 zero)
#define ROFF_BLIN 45056                 // 1024
#define ROFF_H1A  46080                 // 32
#define ROFF_H1B  46112                 // 32
#define ROFF_H2   46144                 // 32
#define ROFF_XCUR 46176                 // 1024
#define RSM_FLOATS 47200
#define RSM_BYTES (RSM_FLOATS * 4)

__global__ __launch_bounds__(128, 1) void recurrence_kernel(
    const float* __restrict__ W_hh1, const float* __restrict__ W_ih2,
    const float* __restrict__ W_hh2, const float* __restrict__ b_ih2,
    const float* __restrict__ b_hh2, const float* __restrict__ W_ih1,
    const float* __restrict__ b_ih1, const float* __restrict__ b_hh1,
    const float* __restrict__ W_lin, const float* __restrict__ b_lin,
    float* __restrict__ out, int Tout, int future) {
    extern __shared__ float sm[];
    float* whh1p = sm + ROFF_WHH1;
    float* wih2p = sm + ROFF_WIH2;
    float* whh2p = sm + ROFF_WHH2;
    float* wlinp = sm + ROFF_WLIN;
    float* blins = sm + ROFF_BLIN;
    float* h1a   = sm + ROFF_H1A;
    float* h1b   = sm + ROFF_H1B;
    float* h2s   = sm + ROFF_H2;
    float* xcur  = sm + ROFF_XCUR;

    const int tid = threadIdx.x;
    const int b = blockIdx.x;
    const int u = tid >> 2;              // unit 0..31 (31 = dummy)
    const int q = tid & 3;               // gate i,f,g,o
    const int srcrow = q * H_SZ + u;     // original gate row (valid when tid<124)
    const int lanebase = (tid & 31) & ~3;
    const bool writer = (q == 0) && (u < H_SZ);

    // --- load padded weight tiles (rows >=124 and k==31 are zero) ---
    for (int i = tid; i < 128 * 32; i += 128) {
        int r = i >> 5, k = i & 31;
        int ru = r >> 2, rq = r & 3;
        int src = rq * H_SZ + ru;
        bool ok = (r < G_SZ) && (k < H_SZ);
        whh1p[i] = ok ? W_hh1[src * H_SZ + k] : 0.f;
        wih2p[i] = ok ? W_ih2[src * H_SZ + k] : 0.f;
        whh2p[i] = ok ? W_hh2[src * H_SZ + k] : 0.f;
    }
    for (int i = tid; i < 1024 * 32; i += 128) {
        int f = i >> 5, k = i & 31;
        wlinp[i] = (k < H_SZ) ? W_lin[f * H_SZ + k] : 0.f;
    }
    for (int i = tid; i < 1024; i += 128) blins[i] = b_lin[i];
    if (tid < 32) { h1a[tid] = 0.f; h1b[tid] = 0.f; h2s[tid] = 0.f; }

    const float myb1 = (tid < G_SZ) ? (b_ih1[srcrow] + b_hh1[srcrow]) : 0.f;
    const float myb2 = (tid < G_SZ) ? (b_ih2[srcrow] + b_hh2[srcrow]) : 0.f;
    float c1 = 0.f, c2 = 0.f;
    __syncthreads();

    // xg column for this thread (padded cols 124..127 are zero)
    const int xgcol = (tid < G_SZ) ? srcrow : tid;
    const float* xgp = g_xg + (size_t)b * T_SZ * XG_STRIDE + xgcol;
    const float* myw1 = whh1p + tid * 32;
    const float* myw2a = wih2p + tid * 32;
    const float* myw2b = whh2p + tid * 32;

    float* h1r = h1a;   // read buffer (h1 at t-1)
    float* h1w = h1b;   // write buffer (h1 at t)

    float cur = __ldcg(xgp);

    // ---------------- teacher-forced recurrence ----------------
    for (int t = 0; t < T_SZ; t++) {
        float nxt = 0.f;
        if (t < T_SZ - 1) nxt = __ldcg(xgp + (size_t)(t + 1) * XG_STRIDE);

        // Phase A: layer-1 gate + layer-2 partial (h2 part), act1
        float a = cur + dot32(myw1, h1r);
        float d2 = myb2 + dot32(myw2b, h2s);
        float myg1 = (q == 2) ? tanh_acc(a) : sigf(a);
        float h1 = lstm_unit(myg1, lanebase, c1);
        if (writer) h1w[u] = h1;
        __syncthreads();

        // Phase B: layer-2 gate (h1 part), act2
        d2 += dot32(myw2a, h1w);
        float myg2 = (q == 2) ? tanh_acc(d2) : sigf(d2);
        float h2 = lstm_unit(myg2, lanebase, c2);
        if (writer) {
            h2s[u] = h2;
            g_h2hist[((size_t)b * T_SZ + t) * 32 + u] = h2;
        }
        cur = nxt;
        { float* tmp = h1r; h1r = h1w; h1w = tmp; }
        __syncthreads();
    }

    // ---------------- autoregressive future steps ----------------
    // xcur = output at t=T-1 (== what outproj writes at column 511)
#pragma unroll
    for (int i = 0; i < 8; i++) {
        int f = tid + i * 128;
        xcur[f] = blins[f] + dot32(wlinp + f * 32, h2s);
    }
    __syncthreads();

    for (int s = 1; s <= future; s++) {
        // Phase A: layer-1 gates = W_ih1 row . xcur + W_hh1 . h1 + b1
        float a = myb1 + dot32(myw1, h1r);
        if (tid < G_SZ) {
            const float4* w4 = (const float4*)(W_ih1 + (size_t)srcrow * F_SZ);
            const float4* x4 = (const float4*)xcur;
            float a0 = 0.f, a1 = 0.f, a2 = 0.f, a3 = 0.f;
#pragma unroll 8
            for (int p = 0; p < 256; p++) {
                float4 w = __ldcg(w4 + p);
                float4 xv = x4[p];
                a0 = fmaf(w.x, xv.x, a0);
                a1 = fmaf(w.y, xv.y, a1);
                a2 = fmaf(w.z, xv.z, a2);
                a3 = fmaf(w.w, xv.w, a3);
            }
            a += (a0 + a1) + (a2 + a3);
        }
        float d2 = myb2 + dot32(myw2b, h2s);
        float myg1 = (q == 2) ? tanh_acc(a) : sigf(a);
        float h1 = lstm_unit(myg1, lanebase, c1);
        if (writer) h1w[u] = h1;
        __syncthreads();

        // Phase B: layer-2 gates, act2
        d2 += dot32(myw2a, h1w);
        float myg2 = (q == 2) ? tanh_acc(d2) : sigf(d2);
        float h2 = lstm_unit(myg2, lanebase, c2);
        if (writer) h2s[u] = h2;
        { float* tmp = h1r; h1r = h1w; h1w = tmp; }
        __syncthreads();

        // Output projection: out_{511+s} = h2 . W_lin^T + b_lin
#pragma unroll
        for (int i = 0; i < 8; i++) {
            int f = tid + i * 128;
            float v = blins[f] + dot32(wlinp + f * 32, h2s);
            xcur[f] = v;
            out[((size_t)b * Tout + (T_SZ - 1) + s) * F_SZ + f] = v;
        }
        __syncthreads();
    }
}

// =================================================================
// Kernel 3: teacher-forced output projection
// =================================================================
__global__ __launch_bounds__(256) void outproj_kernel(
    const float* __restrict__ W_lin, const float* __restrict__ b_lin,
    float* __restrict__ out, int Tout) {
    __shared__ float h2t[16][32];
    const int b = blockIdx.y;
    const int t0 = blockIdx.x * 16;
    const int tid = threadIdx.x;

    const float* src = g_h2hist + ((size_t)b * T_SZ + t0) * 32;
    for (int i = tid; i < 512; i += 256) ((float*)h2t)[i] = src[i];
    __syncthreads();

#pragma unroll
    for (int c = 0; c < 4; c++) {
        int f = tid + c * 256;
        float w[31];
        const float* wrow = W_lin + (size_t)f * 31;
#pragma unroll
        for (int k = 0; k < 31; k++) w[k] = wrow[k];
        float bv = b_lin[f];
#pragma unroll
        for (int tt = 0; tt < 16; tt++) {
            const float4* hp = (const float4*)&h2t[tt][0];
            float a0 = bv, a1 = 0.f, a2 = 0.f, a3 = 0.f;
#pragma unroll
            for (int p = 0; p < 7; p++) {
                float4 h = hp[p];
                a0 = fmaf(w[4 * p + 0], h.x, a0);
                a1 = fmaf(w[4 * p + 1], h.y, a1);
                a2 = fmaf(w[4 * p + 2], h.z, a2);
                a3 = fmaf(w[4 * p + 3], h.w, a3);
            }
            a0 = fmaf(w[28], h2t[tt][28], a0);
            a1 = fmaf(w[29], h2t[tt][29], a1);
            a2 = fmaf(w[30], h2t[tt][30], a2);
            out[((size_t)b * Tout + t0 + tt) * F_SZ + f] = (a0 + a1) + (a2 + a3);
        }
    }
}

// =================================================================
extern "C" void kernel_launch(void* const* d_in, const int* in_sizes, int n_in,
                              void* d_out, int out_size) {
    const float* input = (const float*)d_in[0];
    const float* W_ih1 = (const float*)d_in[1];
    const float* W_hh1 = (const float*)d_in[2];
    const float* b_ih1 = (const float*)d_in[3];
    const float* b_hh1 = (const float*)d_in[4];
    const float* W_ih2 = (const float*)d_in[5];
    const float* W_hh2 = (const float*)d_in[6];
    const float* b_ih2 = (const float*)d_in[7];
    const float* b_hh2 = (const float*)d_in[8];
    const float* W_lin = (const float*)d_in[9];
    const float* b_lin = (const float*)d_in[10];
    float* out = (float*)d_out;

    const int Tout = out_size / (B_SZ * F_SZ);   // 528
    const int future = Tout - T_SZ;              // 16

    cudaFuncSetAttribute(recurrence_kernel,
                         cudaFuncAttributeMaxDynamicSharedMemorySize, RSM_BYTES);

    gemm_xg_kernel<<<ROWS / 128, 256>>>(input, W_ih1, b_ih1, b_hh1);

    recurrence_kernel<<<B_SZ, 128, RSM_BYTES>>>(
        W_hh1, W_ih2, W_hh2, b_ih2, b_hh2, W_ih1, b_ih1, b_hh1,
        W_lin, b_lin, out, Tout, future);

    dim3 g3(T_SZ / 16, B_SZ);
    outproj_kernel<<<g3, 256>>>(W_lin, b_lin, out, Tout);
}

// round 8
// speedup vs baseline: 1.4268x; 1.4268x over previous
#include <cuda_runtime.h>
#include <cstdint>

// Problem constants (dataset-fixed): B=64, T=512, F=1024, H=31, G=4H=124
#define B_SZ 64
#define T_SZ 512
#define F_SZ 1024
#define H_SZ 31
#define G_SZ 124
#define ROWS (B_SZ * T_SZ)      // 32768
#define XG_STRIDE 128           // padded gate stride

// ---------------- scratch (no allocations allowed) ----------------
__device__ float g_xg[(size_t)ROWS * XG_STRIDE];      // gates1 x-part + bias
__device__ float g_h2hist[(size_t)ROWS * 32];         // h2 per step, [b*T+t][32]

// ---------------- fast activations (MUFU; proven accuracy-harmless) -------
__device__ __forceinline__ float sigf(float x) {
    return __fdividef(1.0f, 1.0f + __expf(-x));
}
__device__ __forceinline__ float tanh_f(float x) {
    return fmaf(2.0f, sigf(2.0f * x), -1.0f);
}

// 31-wide dot: register weights x broadcast smem h
__device__ __forceinline__ float dot31r(const float* __restrict__ w,
                                        const float* __restrict__ h, float init) {
    float a0 = init, a1 = 0.f, a2 = 0.f, a3 = 0.f;
#pragma unroll
    for (int k = 0; k < 28; k += 4) {
        a0 = fmaf(w[k + 0], h[k + 0], a0);
        a1 = fmaf(w[k + 1], h[k + 1], a1);
        a2 = fmaf(w[k + 2], h[k + 2], a2);
        a3 = fmaf(w[k + 3], h[k + 3], a3);
    }
    a0 = fmaf(w[28], h[28], a0);
    a1 = fmaf(w[29], h[29], a1);
    a2 = fmaf(w[30], h[30], a2);
    return (a0 + a1) + (a2 + a3);
}

// LSTM pointwise via intra-quad shuffles; every lane of the quad keeps c.
__device__ __forceinline__ float lstm_unit(float myg, int lanebase, float& c) {
    float vi = __shfl_sync(0xffffffffu, myg, lanebase + 0);
    float vf = __shfl_sync(0xffffffffu, myg, lanebase + 1);
    float vg = __shfl_sync(0xffffffffu, myg, lanebase + 2);
    float vo = __shfl_sync(0xffffffffu, myg, lanebase + 3);
    c = vf * c + vi * vg;
    return vo * tanh_f(c);
}

// =================================================================
// Kernel 1: xg[r][g] = x_r . W_ih1[g,:] + b_ih1[g] + b_hh1[g]
// M=32768, N=124(pad128), K=1024. BM=128,BN=128,BK=16, 256 thr, 8x8/thread.
// =================================================================
__global__ __launch_bounds__(256) void gemm_xg_kernel(
    const float* __restrict__ x, const float* __restrict__ W,
    const float* __restrict__ b_ih, const float* __restrict__ b_hh) {
    __shared__ float xs[16][128];   // [k][row]
    __shared__ float ws[16][128];   // [k][col]

    const int tid = threadIdx.x;
    const int row0 = blockIdx.x * 128;
    const int tx = tid & 15;
    const int ty = tid >> 4;
    const int c0 = tx * 8;
    const int r0 = ty * 8;

    float acc[8][8];
#pragma unroll
    for (int i = 0; i < 8; i++)
#pragma unroll
        for (int j = 0; j < 8; j++) acc[i][j] = 0.f;

    for (int k0 = 0; k0 < F_SZ; k0 += 16) {
#pragma unroll
        for (int l = tid; l < 512; l += 256) {
            int r = l >> 2;
            int kq = (l & 3) << 2;
            float4 v = *(const float4*)(x + (size_t)(row0 + r) * F_SZ + k0 + kq);
            xs[kq + 0][r] = v.x; xs[kq + 1][r] = v.y;
            xs[kq + 2][r] = v.z; xs[kq + 3][r] = v.w;
        }
#pragma unroll
        for (int l = tid; l < 512; l += 256) {
            int gc = l >> 2;
            int kq = (l & 3) << 2;
            float4 v = make_float4(0.f, 0.f, 0.f, 0.f);
            if (gc < G_SZ) v = *(const float4*)(W + (size_t)gc * F_SZ + k0 + kq);
            ws[kq + 0][gc] = v.x; ws[kq + 1][gc] = v.y;
            ws[kq + 2][gc] = v.z; ws[kq + 3][gc] = v.w;
        }
        __syncthreads();

#pragma unroll
        for (int kk = 0; kk < 16; kk++) {
            float4 xa = *(const float4*)&xs[kk][r0];
            float4 xb = *(const float4*)&xs[kk][r0 + 4];
            float4 wa = *(const float4*)&ws[kk][c0];
            float4 wb = *(const float4*)&ws[kk][c0 + 4];
            float xr[8] = {xa.x, xa.y, xa.z, xa.w, xb.x, xb.y, xb.z, xb.w};
            float wr[8] = {wa.x, wa.y, wa.z, wa.w, wb.x, wb.y, wb.z, wb.w};
#pragma unroll
            for (int i = 0; i < 8; i++)
#pragma unroll
                for (int j = 0; j < 8; j++)
                    acc[i][j] = fmaf(xr[i], wr[j], acc[i][j]);
        }
        __syncthreads();
    }

    float bs[8];
#pragma unroll
    for (int j = 0; j < 8; j++) {
        int cc = c0 + j;
        bs[j] = (cc < G_SZ) ? (b_ih[cc] + b_hh[cc]) : 0.f;
    }
#pragma unroll
    for (int i = 0; i < 8; i++) {
        int r = row0 + r0 + i;
        float4 lo = make_float4(acc[i][0] + bs[0], acc[i][1] + bs[1],
                                acc[i][2] + bs[2], acc[i][3] + bs[3]);
        float4 hi = make_float4(acc[i][4] + bs[4], acc[i][5] + bs[5],
                                acc[i][6] + bs[6], acc[i][7] + bs[7]);
        *(float4*)&g_xg[(size_t)r * XG_STRIDE + c0] = lo;
        *(float4*)&g_xg[(size_t)r * XG_STRIDE + c0 + 4] = hi;
    }
}

// =================================================================
// Kernel 2: recurrence. Unit-major gates (thread = 4u+q), weights in
// REGISTERS (no weight LDS), broadcast-only smem h, shuffle acts,
// 2 barriers/step, fast MUFU activations.
// =================================================================
#define ROFF_WLIN 0                     // k-major [32][1024] = 32768
#define ROFF_BLIN 32768                 // 1024
#define ROFF_H1A  33792                 // 32
#define ROFF_H1B  33824                 // 32
#define ROFF_H2   33856                 // 32
#define ROFF_XCUR 33888                 // 1024
#define RSM_FLOATS 34912
#define RSM_BYTES (RSM_FLOATS * 4)

__global__ __launch_bounds__(128, 1) void recurrence_kernel(
    const float* __restrict__ W_hh1, const float* __restrict__ W_ih2,
    const float* __restrict__ W_hh2, const float* __restrict__ b_ih2,
    const float* __restrict__ b_hh2, const float* __restrict__ W_ih1,
    const float* __restrict__ b_ih1, const float* __restrict__ b_hh1,
    const float* __restrict__ W_lin, const float* __restrict__ b_lin,
    float* __restrict__ out, int Tout, int future) {
    extern __shared__ float sm[];
    float* wlin_t = sm + ROFF_WLIN;   // [k][f] : conflict-free (stride-1 in f)
    float* blins  = sm + ROFF_BLIN;
    float* h1a    = sm + ROFF_H1A;
    float* h1b    = sm + ROFF_H1B;
    float* h2s    = sm + ROFF_H2;
    float* xcur   = sm + ROFF_XCUR;

    const int tid = threadIdx.x;
    const int b = blockIdx.x;
    const int u = tid >> 2;              // unit 0..31 (31 = dummy)
    const int q = tid & 3;               // gate i,f,g,o
    const bool active = tid < G_SZ;
    const int srcrow = q * H_SZ + u;     // valid only when active
    const int lanebase = (tid & 31) & ~3;
    const bool writer = (q == 0) && (u < H_SZ);

    // --- per-thread weight rows into REGISTERS ---
    float w1[31], w2a[31], w2b[31];
#pragma unroll
    for (int k = 0; k < 31; k++) {
        w1[k]  = active ? W_hh1[srcrow * H_SZ + k] : 0.f;
        w2a[k] = active ? W_ih2[srcrow * H_SZ + k] : 0.f;
        w2b[k] = active ? W_hh2[srcrow * H_SZ + k] : 0.f;
    }
    const float myb1 = active ? (b_ih1[srcrow] + b_hh1[srcrow]) : 0.f;
    const float myb2 = active ? (b_ih2[srcrow] + b_hh2[srcrow]) : 0.f;

    // --- W_lin transposed to k-major smem: wlin_t[k*1024 + f] ---
    for (int i = tid; i < 32 * 1024; i += 128) {
        int k = i >> 10, f = i & 1023;
        wlin_t[i] = (k < H_SZ) ? W_lin[f * H_SZ + k] : 0.f;
    }
    for (int i = tid; i < 1024; i += 128) blins[i] = b_lin[i];
    if (tid < 32) { h1a[tid] = 0.f; h1b[tid] = 0.f; h2s[tid] = 0.f; }
    float c1 = 0.f, c2 = 0.f;
    __syncthreads();

    const int xgcol = active ? srcrow : tid;
    const float* xgp = g_xg + (size_t)b * T_SZ * XG_STRIDE + xgcol;

    float* h1r = h1a;   // h1 at t-1
    float* h1w = h1b;   // h1 at t

    float cur = __ldcg(xgp);

    // ---------------- teacher-forced recurrence ----------------
    for (int t = 0; t < T_SZ; t++) {
        float nxt = 0.f;
        if (t < T_SZ - 1) nxt = __ldcg(xgp + (size_t)(t + 1) * XG_STRIDE);

        // Phase A: layer-1 gate; also layer-2's h2-part (hides latency)
        float a  = dot31r(w1, h1r, cur);
        float d2 = dot31r(w2b, h2s, myb2);
        float myg1 = (q == 2) ? tanh_f(a) : sigf(a);
        float h1 = lstm_unit(myg1, lanebase, c1);
        if (writer) h1w[u] = h1;
        __syncthreads();

        // Phase B: layer-2 gate (h1 part), act2
        d2 = dot31r(w2a, h1w, d2);
        float myg2 = (q == 2) ? tanh_f(d2) : sigf(d2);
        float h2 = lstm_unit(myg2, lanebase, c2);
        if (writer) {
            h2s[u] = h2;
            g_h2hist[((size_t)b * T_SZ + t) * 32 + u] = h2;
        }
        cur = nxt;
        { float* tmp = h1r; h1r = h1w; h1w = tmp; }
        __syncthreads();
    }

    // ---------------- autoregressive future steps ----------------
    // xcur = output at t=T-1 (== outproj's column 511)
#pragma unroll
    for (int i = 0; i < 8; i++) {
        int f = tid + i * 128;
        float a0 = blins[f], a1 = 0.f, a2 = 0.f, a3 = 0.f;
#pragma unroll
        for (int k = 0; k < 28; k += 4) {
            a0 = fmaf(wlin_t[(k + 0) * 1024 + f], h2s[k + 0], a0);
            a1 = fmaf(wlin_t[(k + 1) * 1024 + f], h2s[k + 1], a1);
            a2 = fmaf(wlin_t[(k + 2) * 1024 + f], h2s[k + 2], a2);
            a3 = fmaf(wlin_t[(k + 3) * 1024 + f], h2s[k + 3], a3);
        }
        a0 = fmaf(wlin_t[28 * 1024 + f], h2s[28], a0);
        a1 = fmaf(wlin_t[29 * 1024 + f], h2s[29], a1);
        a2 = fmaf(wlin_t[30 * 1024 + f], h2s[30], a2);
        xcur[f] = (a0 + a1) + (a2 + a3);
    }
    __syncthreads();

    for (int s = 1; s <= future; s++) {
        // Phase A: gates1 = W_ih1 row . xcur + W_hh1 . h1 + b1
        float a = dot31r(w1, h1r, myb1);
        if (active) {
            const float4* w4 = (const float4*)(W_ih1 + (size_t)srcrow * F_SZ);
            const float4* x4 = (const float4*)xcur;
            float a0 = 0.f, a1 = 0.f, a2 = 0.f, a3 = 0.f;
#pragma unroll 8
            for (int p = 0; p < 256; p++) {
                float4 w = __ldcg(w4 + p);
                float4 xv = x4[p];
                a0 = fmaf(w.x, xv.x, a0);
                a1 = fmaf(w.y, xv.y, a1);
                a2 = fmaf(w.z, xv.z, a2);
                a3 = fmaf(w.w, xv.w, a3);
            }
            a += (a0 + a1) + (a2 + a3);
        }
        float d2 = dot31r(w2b, h2s, myb2);
        float myg1 = (q == 2) ? tanh_f(a) : sigf(a);
        float h1 = lstm_unit(myg1, lanebase, c1);
        if (writer) h1w[u] = h1;
        __syncthreads();

        // Phase B
        d2 = dot31r(w2a, h1w, d2);
        float myg2 = (q == 2) ? tanh_f(d2) : sigf(d2);
        float h2 = lstm_unit(myg2, lanebase, c2);
        if (writer) h2s[u] = h2;
        { float* tmp = h1r; h1r = h1w; h1w = tmp; }
        __syncthreads();

        // out_{511+s} = h2 . W_lin^T + b_lin ; also next x
#pragma unroll
        for (int i = 0; i < 8; i++) {
            int f = tid + i * 128;
            float a0 = blins[f], a1 = 0.f, a2 = 0.f, a3 = 0.f;
#pragma unroll
            for (int k = 0; k < 28; k += 4) {
                a0 = fmaf(wlin_t[(k + 0) * 1024 + f], h2s[k + 0], a0);
                a1 = fmaf(wlin_t[(k + 1) * 1024 + f], h2s[k + 1], a1);
                a2 = fmaf(wlin_t[(k + 2) * 1024 + f], h2s[k + 2], a2);
                a3 = fmaf(wlin_t[(k + 3) * 1024 + f], h2s[k + 3], a3);
            }
            a0 = fmaf(wlin_t[28 * 1024 + f], h2s[28], a0);
            a1 = fmaf(wlin_t[29 * 1024 + f], h2s[29], a1);
            a2 = fmaf(wlin_t[30 * 1024 + f], h2s[30], a2);
            float v = (a0 + a1) + (a2 + a3);
            xcur[f] = v;
            out[((size_t)b * Tout + (T_SZ - 1) + s) * F_SZ + f] = v;
        }
        __syncthreads();
    }
}

// =================================================================
// Kernel 3: teacher-forced output projection
// =================================================================
__global__ __launch_bounds__(256) void outproj_kernel(
    const float* __restrict__ W_lin, const float* __restrict__ b_lin,
    float* __restrict__ out, int Tout) {
    __shared__ float h2t[16][32];
    const int b = blockIdx.y;
    const int t0 = blockIdx.x * 16;
    const int tid = threadIdx.x;

    const float* src = g_h2hist + ((size_t)b * T_SZ + t0) * 32;
    for (int i = tid; i < 512; i += 256) ((float*)h2t)[i] = src[i];
    __syncthreads();

#pragma unroll
    for (int c = 0; c < 4; c++) {
        int f = tid + c * 256;
        float w[31];
        const float* wrow = W_lin + (size_t)f * 31;
#pragma unroll
        for (int k = 0; k < 31; k++) w[k] = wrow[k];
        float bv = b_lin[f];
#pragma unroll
        for (int tt = 0; tt < 16; tt++) {
            const float4* hp = (const float4*)&h2t[tt][0];
            float a0 = bv, a1 = 0.f, a2 = 0.f, a3 = 0.f;
#pragma unroll
            for (int p = 0; p < 7; p++) {
                float4 h = hp[p];
                a0 = fmaf(w[4 * p + 0], h.x, a0);
                a1 = fmaf(w[4 * p + 1], h.y, a1);
                a2 = fmaf(w[4 * p + 2], h.z, a2);
                a3 = fmaf(w[4 * p + 3], h.w, a3);
            }
            a0 = fmaf(w[28], h2t[tt][28], a0);
            a1 = fmaf(w[29], h2t[tt][29], a1);
            a2 = fmaf(w[30], h2t[tt][30], a2);
            out[((size_t)b * Tout + t0 + tt) * F_SZ + f] = (a0 + a1) + (a2 + a3);
        }
    }
}

// =================================================================
extern "C" void kernel_launch(void* const* d_in, const int* in_sizes, int n_in,
                              void* d_out, int out_size) {
    const float* input = (const float*)d_in[0];
    const float* W_ih1 = (const float*)d_in[1];
    const float* W_hh1 = (const float*)d_in[2];
    const float* b_ih1 = (const float*)d_in[3];
    const float* b_hh1 = (const float*)d_in[4];
    const float* W_ih2 = (const float*)d_in[5];
    const float* W_hh2 = (const float*)d_in[6];
    const float* b_ih2 = (const float*)d_in[7];
    const float* b_hh2 = (const float*)d_in[8];
    const float* W_lin = (const float*)d_in[9];
    const float* b_lin = (const float*)d_in[10];
    float* out = (float*)d_out;

    const int Tout = out_size / (B_SZ * F_SZ);   // 528
    const int future = Tout - T_SZ;              // 16

    cudaFuncSetAttribute(recurrence_kernel,
                         cudaFuncAttributeMaxDynamicSharedMemorySize, RSM_BYTES);

    gemm_xg_kernel<<<ROWS / 128, 256>>>(input, W_ih1, b_ih1, b_hh1);

    recurrence_kernel<<<B_SZ, 128, RSM_BYTES>>>(
        W_hh1, W_ih2, W_hh2, b_ih2, b_hh2, W_ih1, b_ih1, b_hh1,
        W_lin, b_lin, out, Tout, future);

    dim3 g3(T_SZ / 16, B_SZ);
    outproj_kernel<<<g3, 256>>>(W_lin, b_lin, out, Tout);
}